// round 2
// baseline (speedup 1.0000x reference)
#include <cuda_runtime.h>

// ---------------------------------------------------------------------------
// AdaptiveUnivariateFunction: out = linear_spline(normalize(x); cp, uniform knots)
//   xn  = (x - min(x)) / (max(x) - min(x) + 1e-6)   -> in [0,1)
//   idx = clamp(floor(xn*31), 0, 30); t = xn*31 - idx
//   out = cp[idx] + t*(cp[idx+1]-cp[idx])
//
// Pass 1: per-block min/max -> fixed slots in __device__ partials[] (no atomics,
//         no init kernel: every slot is overwritten deterministically each call).
// Pass 2: per-block reduce of partials (L2-broadcast, hidden), then transform.
//         Pass 1 walks ascending, pass 2 descending -> pass 2's first ~126MB of
//         reads hit pass 1's L2 residue. Pass-2 traffic uses .cs (evict-first).
// ---------------------------------------------------------------------------

#define NPART 1184              // grid size for both passes (148 SMs x 8 blocks)
#define NTHREADS 256

__device__ float2 g_partials[NPART];   // (min, max) per pass-1 block

// ---------------------------------------------------------------------------
// Pass 1: block-local min/max over a grid-stride sweep (ascending).
// ---------------------------------------------------------------------------
__global__ void __launch_bounds__(NTHREADS, 8)
auf_minmax_kernel(const float* __restrict__ xs, int n) {
    const float4* __restrict__ x4 = (const float4*)xs;
    const int nv4 = n >> 2;

    float vmin = 3.402823466e38f;
    float vmax = -3.402823466e38f;

    const int stride = gridDim.x * blockDim.x;
    #pragma unroll 2
    for (int i = blockIdx.x * blockDim.x + threadIdx.x; i < nv4; i += stride) {
        float4 v = x4[i];
        vmin = fminf(vmin, fminf(fminf(v.x, v.y), fminf(v.z, v.w)));
        vmax = fmaxf(vmax, fmaxf(fmaxf(v.x, v.y), fmaxf(v.z, v.w)));
    }
    // scalar tail (defensive; n % 4 == 0 for this problem)
    if (blockIdx.x == 0 && threadIdx.x < (n & 3)) {
        float v = xs[(nv4 << 2) + threadIdx.x];
        vmin = fminf(vmin, v);
        vmax = fmaxf(vmax, v);
    }

    // warp reduce
    #pragma unroll
    for (int o = 16; o; o >>= 1) {
        vmin = fminf(vmin, __shfl_xor_sync(0xFFFFFFFFu, vmin, o));
        vmax = fmaxf(vmax, __shfl_xor_sync(0xFFFFFFFFu, vmax, o));
    }

    // block reduce -> one deterministic global write per block
    __shared__ float smin[8], smax[8];
    const int wid = threadIdx.x >> 5;
    const int lid = threadIdx.x & 31;
    if (lid == 0) { smin[wid] = vmin; smax[wid] = vmax; }
    __syncthreads();
    if (threadIdx.x == 0) {
        float bmin = smin[0], bmax = smax[0];
        #pragma unroll
        for (int w = 1; w < 8; w++) {
            bmin = fminf(bmin, smin[w]);
            bmax = fmaxf(bmax, smax[w]);
        }
        g_partials[blockIdx.x] = make_float2(bmin, bmax);
    }
}

// ---------------------------------------------------------------------------
// Pass 2: reduce partials (cheap, L2-broadcast), then spline transform
// over a DESCENDING grid-stride sweep with evict-first traffic.
// ---------------------------------------------------------------------------
__device__ __forceinline__ float auf_eval(float x, float S, float B,
                                          const float2* __restrict__ tab) {
    float xn31 = fmaf(x, S, B);          // xn * 31
    int idx = (int)xn31;                 // trunc == floor (xn31 >= -eps)
    idx = max(0, min(idx, 30));          // boundary rounding is value-neutral
    float2 ad = tab[idx];                // (cp[idx], cp[idx+1]-cp[idx])
    return fmaf(xn31 - (float)idx, ad.y, ad.x);
}

__global__ void __launch_bounds__(NTHREADS, 8)
auf_apply_kernel(const float* __restrict__ xs,
                 const float* __restrict__ cp,
                 float* __restrict__ outs,
                 int n) {
    __shared__ float2 tab[32];
    __shared__ float s_minmax[16];   // [0..7]=warp mins, [8..15]=warp maxs
    __shared__ float s_SB[2];        // broadcast (S, B)

    // --- spline table ---
    if (threadIdx.x < 32) {
        int i = (threadIdx.x < 31) ? (int)threadIdx.x : 30;  // slot 31 dup of 30
        float c0 = cp[i];
        float c1 = cp[i + 1];
        tab[threadIdx.x] = make_float2(c0, c1 - c0);
    }

    // --- reduce the 1184 pass-1 partials (every block; ~9.5KB L2 reads) ---
    {
        float vmin = 3.402823466e38f;
        float vmax = -3.402823466e38f;
        for (int i = threadIdx.x; i < NPART; i += NTHREADS) {
            float2 p = g_partials[i];
            vmin = fminf(vmin, p.x);
            vmax = fmaxf(vmax, p.y);
        }
        #pragma unroll
        for (int o = 16; o; o >>= 1) {
            vmin = fminf(vmin, __shfl_xor_sync(0xFFFFFFFFu, vmin, o));
            vmax = fmaxf(vmax, __shfl_xor_sync(0xFFFFFFFFu, vmax, o));
        }
        const int wid = threadIdx.x >> 5;
        if ((threadIdx.x & 31) == 0) { s_minmax[wid] = vmin; s_minmax[8 + wid] = vmax; }
        __syncthreads();
        if (threadIdx.x == 0) {
            float bmin = s_minmax[0], bmax = s_minmax[8];
            #pragma unroll
            for (int w = 1; w < 8; w++) {
                bmin = fminf(bmin, s_minmax[w]);
                bmax = fmaxf(bmax, s_minmax[8 + w]);
            }
            float S = 31.0f / (bmax - bmin + 1e-6f);
            s_SB[0] = S;
            s_SB[1] = -bmin * S;
        }
        __syncthreads();
    }
    const float S = s_SB[0];
    const float B = s_SB[1];

    // --- transform (descending; .cs evict-first for read-once/write-once) ---
    const float4* __restrict__ x4 = (const float4*)xs;
    float4* __restrict__ o4 = (float4*)outs;
    const int nv4 = n >> 2;

    const int stride = gridDim.x * blockDim.x;
    #pragma unroll 2
    for (int i = blockIdx.x * blockDim.x + threadIdx.x; i < nv4; i += stride) {
        const int j = nv4 - 1 - i;       // reversed traversal for L2 reuse
        float4 v = __ldcs(&x4[j]);
        float4 r;
        r.x = auf_eval(v.x, S, B, tab);
        r.y = auf_eval(v.y, S, B, tab);
        r.z = auf_eval(v.z, S, B, tab);
        r.w = auf_eval(v.w, S, B, tab);
        __stcs(&o4[j], r);
    }
    // scalar tail
    if (blockIdx.x == gridDim.x - 1 && threadIdx.x < (n & 3)) {
        const int e = (nv4 << 2) + threadIdx.x;
        outs[e] = auf_eval(xs[e], S, B, tab);
    }
}

// ---------------------------------------------------------------------------
// Launch: minmax -> apply. Kernel launches only; no sync, no allocation.
// ---------------------------------------------------------------------------
extern "C" void kernel_launch(void* const* d_in, const int* in_sizes, int n_in,
                              void* d_out, int out_size) {
    const float* x  = (const float*)d_in[0];   // (64, 1048576) fp32
    const float* cp = (const float*)d_in[1];   // (32,) control points
    // d_in[2] = knots: uniform linspace(0,1,32) -> analytic, not needed
    const int n = in_sizes[0];

    auf_minmax_kernel<<<NPART, NTHREADS>>>(x, n);
    auf_apply_kernel<<<NPART, NTHREADS>>>(x, cp, (float*)d_out, n);
}

// round 3
// speedup vs baseline: 1.0020x; 1.0020x over previous
#include <cuda_runtime.h>

// ---------------------------------------------------------------------------
// AdaptiveUnivariateFunction, fused single persistent kernel:
//   phase 1: per-block min/max over a grid-stride slice (ascending)
//   grid barrier (epoch ticket; exactly one wave resident -> no deadlock)
//   phase 2: linear-spline transform, each block re-walking ITS OWN indices
//            in reverse so its freshest L2 lines are re-read first.
//
//   xn  = (x - min) / (max - min + 1e-6) in [0,1)
//   idx = clamp(floor(xn*31), 0, 30); t = xn*31 - idx
//   out = cp[idx] + t*(cp[idx+1]-cp[idx])
// ---------------------------------------------------------------------------

#define NPART 1184              // 148 SMs x 8 blocks -> exactly one wave
#define NTHREADS 256

__device__ float2 g_partials[NPART];     // (min,max) per block
__device__ unsigned int g_count;         // barrier arrivals (reset each call)
__device__ unsigned int g_release;       // barrier epoch (monotone, wrap-safe)

__device__ __forceinline__ unsigned int ld_acq(const unsigned int* p) {
    unsigned int v;
    asm volatile("ld.global.acquire.gpu.u32 %0, [%1];" : "=r"(v) : "l"(p));
    return v;
}

__device__ __forceinline__ float auf_eval(float x, float S, float B,
                                          const float2* __restrict__ tab) {
    float xn31 = fmaf(x, S, B);          // xn * 31
    int idx = (int)xn31;                 // trunc == floor here
    idx = max(0, min(idx, 30));          // boundary rounding value-neutral
    float2 ad = tab[idx];                // (cp[idx], cp[idx+1]-cp[idx])
    return fmaf(xn31 - (float)idx, ad.y, ad.x);
}

__global__ void __launch_bounds__(NTHREADS, 8)
auf_fused_kernel(const float* __restrict__ xs,
                 const float* __restrict__ cp,
                 float* __restrict__ outs,
                 int n) {
    __shared__ float2 tab[32];
    __shared__ float s_red[16];          // warp partials: [0..7]=min [8..15]=max
    __shared__ float s_SB[2];

    // Pre-arrival epoch (safe: no release can happen until THIS block arrives)
    unsigned int epoch0 = 0;
    if (threadIdx.x == 0) epoch0 = ld_acq(&g_release);

    // Spline table: (cp[i], cp[i+1]-cp[i]); slot 31 duplicates 30
    if (threadIdx.x < 32) {
        int i = (threadIdx.x < 31) ? (int)threadIdx.x : 30;
        float c0 = cp[i];
        float c1 = cp[i + 1];
        tab[threadIdx.x] = make_float2(c0, c1 - c0);
    }

    const float4* __restrict__ x4 = (const float4*)xs;
    const int nv4 = n >> 2;
    const int tid0 = blockIdx.x * NTHREADS + (int)threadIdx.x;
    const int stride = NPART * NTHREADS;

    // ---------------- phase 1: min/max (ascending, L2-allocating) ----------
    float vmin = 3.402823466e38f;
    float vmax = -3.402823466e38f;

    #pragma unroll 2
    for (int i = tid0; i < nv4; i += stride) {
        float4 v = x4[i];
        vmin = fminf(vmin, fminf(fminf(v.x, v.y), fminf(v.z, v.w)));
        vmax = fmaxf(vmax, fmaxf(fmaxf(v.x, v.y), fmaxf(v.z, v.w)));
    }
    if (blockIdx.x == 0 && threadIdx.x < (n & 3)) {       // scalar tail
        float v = xs[(nv4 << 2) + threadIdx.x];
        vmin = fminf(vmin, v);
        vmax = fmaxf(vmax, v);
    }

    #pragma unroll
    for (int o = 16; o; o >>= 1) {
        vmin = fminf(vmin, __shfl_xor_sync(0xFFFFFFFFu, vmin, o));
        vmax = fmaxf(vmax, __shfl_xor_sync(0xFFFFFFFFu, vmax, o));
    }
    const int wid = threadIdx.x >> 5;
    if ((threadIdx.x & 31) == 0) { s_red[wid] = vmin; s_red[8 + wid] = vmax; }
    __syncthreads();
    if (threadIdx.x == 0) {
        float bmin = s_red[0], bmax = s_red[8];
        #pragma unroll
        for (int w = 1; w < 8; w++) {
            bmin = fminf(bmin, s_red[w]);
            bmax = fmaxf(bmax, s_red[8 + w]);
        }
        g_partials[blockIdx.x] = make_float2(bmin, bmax);
    }

    // ---------------- grid barrier (epoch ticket, wrap-safe) ---------------
    __threadfence();                                  // partials visible
    if (threadIdx.x == 0) {
        unsigned int old = atomicAdd(&g_count, 1u);
        if (old == NPART - 1) {
            atomicExch(&g_count, 0u);                 // reset for next call
            __threadfence();
            atomicAdd(&g_release, 1u);                // release everyone
        } else {
            while (ld_acq(&g_release) == epoch0) __nanosleep(32);
        }
    }
    __syncthreads();

    // ---------------- reduce partials -> (S, B) ----------------------------
    {
        float rmin = 3.402823466e38f;
        float rmax = -3.402823466e38f;
        for (int i = threadIdx.x; i < NPART; i += NTHREADS) {
            float2 p = g_partials[i];
            rmin = fminf(rmin, p.x);
            rmax = fmaxf(rmax, p.y);
        }
        #pragma unroll
        for (int o = 16; o; o >>= 1) {
            rmin = fminf(rmin, __shfl_xor_sync(0xFFFFFFFFu, rmin, o));
            rmax = fmaxf(rmax, __shfl_xor_sync(0xFFFFFFFFu, rmax, o));
        }
        if ((threadIdx.x & 31) == 0) { s_red[wid] = rmin; s_red[8 + wid] = rmax; }
        __syncthreads();
        if (threadIdx.x == 0) {
            float bmin = s_red[0], bmax = s_red[8];
            #pragma unroll
            for (int w = 1; w < 8; w++) {
                bmin = fminf(bmin, s_red[w]);
                bmax = fmaxf(bmax, s_red[8 + w]);
            }
            float S = 31.0f / (bmax - bmin + 1e-6f);
            s_SB[0] = S;
            s_SB[1] = -bmin * S;
        }
        __syncthreads();
    }
    const float S = s_SB[0];
    const float B = s_SB[1];

    // ---------------- phase 2: transform, SAME indices in REVERSE ----------
    // First re-reads = this thread's most recently loaded lines -> L2 hits.
    float4* __restrict__ o4 = (float4*)outs;
    if (tid0 < nv4) {
        const int last = tid0 + ((nv4 - 1 - tid0) / stride) * stride;
        #pragma unroll 2
        for (int j = last; j >= 0; j -= stride) {
            float4 v = __ldcs(&x4[j]);
            float4 r;
            r.x = auf_eval(v.x, S, B, tab);
            r.y = auf_eval(v.y, S, B, tab);
            r.z = auf_eval(v.z, S, B, tab);
            r.w = auf_eval(v.w, S, B, tab);
            __stcs(&o4[j], r);
        }
    }
    if (blockIdx.x == 0 && threadIdx.x < (n & 3)) {       // scalar tail
        const int e = (nv4 << 2) + threadIdx.x;
        outs[e] = auf_eval(xs[e], S, B, tab);
    }
}

// ---------------------------------------------------------------------------
// Launch: ONE kernel. No sync, no allocation -> graph-capturable.
// ---------------------------------------------------------------------------
extern "C" void kernel_launch(void* const* d_in, const int* in_sizes, int n_in,
                              void* d_out, int out_size) {
    const float* x  = (const float*)d_in[0];   // (64, 1048576) fp32
    const float* cp = (const float*)d_in[1];   // (32,) control points
    // d_in[2] = knots: uniform linspace(0,1,32) -> analytic, unused
    const int n = in_sizes[0];

    auf_fused_kernel<<<NPART, NTHREADS>>>(x, cp, (float*)d_out, n);
}

// round 4
// speedup vs baseline: 1.0462x; 1.0441x over previous
#include <cuda_runtime.h>

// ---------------------------------------------------------------------------
// AdaptiveUnivariateFunction: out = linear_spline(normalize(x); cp, uniform knots)
//   xn = (x - min)/(max - min + 1e-6) in [0,1)
//   idx = clamp(floor(xn*31),0,30); t = xn*31-idx
//   out = cp[idx] + t*(cp[idx+1]-cp[idx])
//
// Round-4 strategy: passive L2 residue doesn't survive (measured ~26MB of a
// possible 126MB). So FORCE it: pass 1 reads the last 96MB of x with an
// L2::evict_last cache-hint policy (pinned), everything else evict-first.
// Pass 2 walks descending (pinned-tail first) with .cs loads/stores so the
// out stream never displaces pinned x lines. Expected apply DRAM reads:
// 256MB -> ~160MB.
// ---------------------------------------------------------------------------

#define NPART 1184              // 148 SMs x 8 blocks
#define NTHREADS 256
#define PIN_V4   6291456        // 96 MB / 16 B: tail float4s pinned in L2

__device__ float2 g_partials[NPART];   // (min,max) per pass-1 block

// float4 load with L2::evict_last cache-hint (pin in L2)
__device__ __forceinline__ float4 ld_pin(const float4* p, unsigned long long pol) {
    float4 v;
    asm volatile("ld.global.L2::cache_hint.v4.f32 {%0,%1,%2,%3}, [%4], %5;"
                 : "=f"(v.x), "=f"(v.y), "=f"(v.z), "=f"(v.w)
                 : "l"(p), "l"(pol));
    return v;
}

__device__ __forceinline__ float auf_eval(float x, float S, float B,
                                          const float2* __restrict__ tab) {
    float xn31 = fmaf(x, S, B);          // xn * 31
    int idx = (int)xn31;                 // trunc == floor here
    idx = max(0, min(idx, 30));          // boundary rounding value-neutral
    float2 ad = tab[idx];                // (cp[idx], cp[idx+1]-cp[idx])
    return fmaf(xn31 - (float)idx, ad.y, ad.x);
}

// ---------------------------------------------------------------------------
// Pass 1: block min/max. Early region .cs (streaming), tail region pinned.
// ---------------------------------------------------------------------------
__global__ void __launch_bounds__(NTHREADS, 8)
auf_minmax_kernel(const float* __restrict__ xs, int n) {
    const float4* __restrict__ x4 = (const float4*)xs;
    const int nv4 = n >> 2;
    const int pin_start = (nv4 > PIN_V4) ? (nv4 - PIN_V4) : 0;

    unsigned long long pol;
    asm volatile("createpolicy.fractional.L2::evict_last.b64 %0, 1.0;" : "=l"(pol));

    float vmin = 3.402823466e38f;
    float vmax = -3.402823466e38f;

    const int stride = NPART * NTHREADS;
    int i = blockIdx.x * NTHREADS + (int)threadIdx.x;

    // early region: streaming, keep L2 clean
    #pragma unroll 4
    for (; i < pin_start; i += stride) {
        float4 v = __ldcs(&x4[i]);
        vmin = fminf(vmin, fminf(fminf(v.x, v.y), fminf(v.z, v.w)));
        vmax = fmaxf(vmax, fmaxf(fmaxf(v.x, v.y), fmaxf(v.z, v.w)));
    }
    // tail region: pin in L2 for pass 2
    #pragma unroll 4
    for (; i < nv4; i += stride) {
        float4 v = ld_pin(&x4[i], pol);
        vmin = fminf(vmin, fminf(fminf(v.x, v.y), fminf(v.z, v.w)));
        vmax = fmaxf(vmax, fmaxf(fmaxf(v.x, v.y), fmaxf(v.z, v.w)));
    }
    // scalar tail (defensive; n % 4 == 0 here)
    if (blockIdx.x == 0 && threadIdx.x < (n & 3)) {
        float v = xs[(nv4 << 2) + threadIdx.x];
        vmin = fminf(vmin, v);
        vmax = fmaxf(vmax, v);
    }

    #pragma unroll
    for (int o = 16; o; o >>= 1) {
        vmin = fminf(vmin, __shfl_xor_sync(0xFFFFFFFFu, vmin, o));
        vmax = fmaxf(vmax, __shfl_xor_sync(0xFFFFFFFFu, vmax, o));
    }
    __shared__ float smin[8], smax[8];
    const int wid = threadIdx.x >> 5;
    if ((threadIdx.x & 31) == 0) { smin[wid] = vmin; smax[wid] = vmax; }
    __syncthreads();
    if (threadIdx.x == 0) {
        float bmin = smin[0], bmax = smax[0];
        #pragma unroll
        for (int w = 1; w < 8; w++) {
            bmin = fminf(bmin, smin[w]);
            bmax = fmaxf(bmax, smax[w]);
        }
        g_partials[blockIdx.x] = make_float2(bmin, bmax);
    }
}

// ---------------------------------------------------------------------------
// Pass 2: reduce partials, then transform descending (pinned tail first).
// ---------------------------------------------------------------------------
__global__ void __launch_bounds__(NTHREADS, 8)
auf_apply_kernel(const float* __restrict__ xs,
                 const float* __restrict__ cp,
                 float* __restrict__ outs,
                 int n) {
    __shared__ float2 tab[32];
    __shared__ float s_red[16];
    __shared__ float s_SB[2];

    if (threadIdx.x < 32) {
        int i = (threadIdx.x < 31) ? (int)threadIdx.x : 30;  // slot 31 dup of 30
        float c0 = cp[i];
        float c1 = cp[i + 1];
        tab[threadIdx.x] = make_float2(c0, c1 - c0);
    }

    // reduce the 1184 pass-1 partials (small, L2-broadcast)
    {
        float rmin = 3.402823466e38f;
        float rmax = -3.402823466e38f;
        for (int i = threadIdx.x; i < NPART; i += NTHREADS) {
            float2 p = g_partials[i];
            rmin = fminf(rmin, p.x);
            rmax = fmaxf(rmax, p.y);
        }
        #pragma unroll
        for (int o = 16; o; o >>= 1) {
            rmin = fminf(rmin, __shfl_xor_sync(0xFFFFFFFFu, rmin, o));
            rmax = fmaxf(rmax, __shfl_xor_sync(0xFFFFFFFFu, rmax, o));
        }
        const int wid = threadIdx.x >> 5;
        if ((threadIdx.x & 31) == 0) { s_red[wid] = rmin; s_red[8 + wid] = rmax; }
        __syncthreads();
        if (threadIdx.x == 0) {
            float bmin = s_red[0], bmax = s_red[8];
            #pragma unroll
            for (int w = 1; w < 8; w++) {
                bmin = fminf(bmin, s_red[w]);
                bmax = fmaxf(bmax, s_red[8 + w]);
            }
            float S = 31.0f / (bmax - bmin + 1e-6f);
            s_SB[0] = S;
            s_SB[1] = -bmin * S;
        }
        __syncthreads();
    }
    const float S = s_SB[0];
    const float B = s_SB[1];

    // transform: global-descending so the pinned tail is consumed first;
    // .cs loads (hit pinned lines, demote on consume) + .cs stores (never
    // displace pinned x lines).
    const float4* __restrict__ x4 = (const float4*)xs;
    float4* __restrict__ o4 = (float4*)outs;
    const int nv4 = n >> 2;

    const int stride = NPART * NTHREADS;
    #pragma unroll 2
    for (int i = blockIdx.x * NTHREADS + (int)threadIdx.x; i < nv4; i += stride) {
        const int j = nv4 - 1 - i;
        float4 v = __ldcs(&x4[j]);
        float4 r;
        r.x = auf_eval(v.x, S, B, tab);
        r.y = auf_eval(v.y, S, B, tab);
        r.z = auf_eval(v.z, S, B, tab);
        r.w = auf_eval(v.w, S, B, tab);
        __stcs(&o4[j], r);
    }
    // scalar tail
    if (blockIdx.x == NPART - 1 && threadIdx.x < (n & 3)) {
        const int e = (nv4 << 2) + threadIdx.x;
        outs[e] = auf_eval(xs[e], S, B, tab);
    }
}

// ---------------------------------------------------------------------------
// Launch: minmax -> apply. Kernel launches only; no sync, no allocation.
// ---------------------------------------------------------------------------
extern "C" void kernel_launch(void* const* d_in, const int* in_sizes, int n_in,
                              void* d_out, int out_size) {
    const float* x  = (const float*)d_in[0];   // (64, 1048576) fp32
    const float* cp = (const float*)d_in[1];   // (32,) control points
    // d_in[2] = knots: uniform linspace(0,1,32) -> analytic, unused
    const int n = in_sizes[0];

    auf_minmax_kernel<<<NPART, NTHREADS>>>(x, n);
    auf_apply_kernel<<<NPART, NTHREADS>>>(x, cp, (float*)d_out, n);
}

// round 5
// speedup vs baseline: 1.0497x; 1.0034x over previous
#include <cuda_runtime.h>

// ---------------------------------------------------------------------------
// AdaptiveUnivariateFunction — fused persistent kernel.
//   xn = (x - min)/(max - min + 1e-6) in [0,1)
//   out = cp[idx] + t*(cp[idx+1]-cp[idx]),  idx=clamp(floor(xn*31),0,30)
//
// phase 1: grid-stride min/max (ascending). Early 160MB -> .cs streaming;
//          last 96MB -> L2::evict_last pin (feeds phase-2 reuse).
// barrier: arrival atomics fold (min,max) into a ping-pong global slot;
//          LAST block computes (S,B), publishes, resets the other slot
//          (next replay), releases. Post-barrier cost per block = 8B load.
// phase 2: each thread re-walks ITS OWN indices in REVERSE (freshest lines
//          first), .cs loads + .cs stores (never displace pinned x).
// ---------------------------------------------------------------------------

#define NPART 1184              // 148 SMs x 8 blocks -> exactly one wave
#define NTHREADS 256
#define PIN_V4   6291456        // 96 MB / 16 B: tail float4s pinned in L2

// ping-pong (min,max) accumulators in flipped-uint space; slot = epoch & 1
__device__ unsigned int g_mm[2][2] = {{0xFFFFFFFFu, 0u}, {0xFFFFFFFFu, 0u}};
__device__ float2 g_sb[2];               // published (S, B) per slot
__device__ unsigned int g_count;         // barrier arrivals
__device__ unsigned int g_release;       // barrier epoch (monotone)

__device__ __forceinline__ unsigned int ld_acq(const unsigned int* p) {
    unsigned int v;
    asm volatile("ld.global.acquire.gpu.u32 %0, [%1];" : "=r"(v) : "l"(p));
    return v;
}
// order-preserving float<->uint (monotone under unsigned compare)
__device__ __forceinline__ unsigned int flipf(float f) {
    unsigned int u = __float_as_uint(f);
    return u ^ ((unsigned int)(-(int)(u >> 31)) | 0x80000000u);
}
__device__ __forceinline__ float unflipf(unsigned int u) {
    return __uint_as_float(u ^ (((u >> 31) - 1u) | 0x80000000u));
}
// float4 load with L2::evict_last cache-hint
__device__ __forceinline__ float4 ld_pin(const float4* p, unsigned long long pol) {
    float4 v;
    asm volatile("ld.global.L2::cache_hint.v4.f32 {%0,%1,%2,%3}, [%4], %5;"
                 : "=f"(v.x), "=f"(v.y), "=f"(v.z), "=f"(v.w)
                 : "l"(p), "l"(pol));
    return v;
}

__device__ __forceinline__ float auf_eval(float x, float S, float B,
                                          const float2* __restrict__ tab) {
    float xn31 = fmaf(x, S, B);          // xn * 31
    int idx = (int)xn31;                 // trunc == floor here
    idx = max(0, min(idx, 30));          // boundary rounding value-neutral
    float2 ad = tab[idx];                // (cp[idx], cp[idx+1]-cp[idx])
    return fmaf(xn31 - (float)idx, ad.y, ad.x);
}

__global__ void __launch_bounds__(NTHREADS, 8)
auf_fused_kernel(const float* __restrict__ xs,
                 const float* __restrict__ cp,
                 float* __restrict__ outs,
                 int n) {
    __shared__ float2 tab[32];
    __shared__ float smin[8], smax[8];
    __shared__ float s_SB[2];

    // epoch (pre-arrival read is safe: release needs THIS block's arrival)
    unsigned int epoch0 = 0;
    if (threadIdx.x == 0) epoch0 = ld_acq(&g_release);

    // spline table: (cp[i], cp[i+1]-cp[i]); slot 31 duplicates 30
    if (threadIdx.x < 32) {
        int i = (threadIdx.x < 31) ? (int)threadIdx.x : 30;
        float c0 = cp[i];
        float c1 = cp[i + 1];
        tab[threadIdx.x] = make_float2(c0, c1 - c0);
    }

    unsigned long long pol;
    asm volatile("createpolicy.fractional.L2::evict_last.b64 %0, 1.0;" : "=l"(pol));

    const float4* __restrict__ x4 = (const float4*)xs;
    const int nv4 = n >> 2;
    const int pin_start = (nv4 > PIN_V4) ? (nv4 - PIN_V4) : 0;
    const int tid0 = blockIdx.x * NTHREADS + (int)threadIdx.x;
    const int stride = NPART * NTHREADS;

    // ------------------- phase 1: min/max -------------------
    float vmin = 3.402823466e38f;
    float vmax = -3.402823466e38f;

    int i = tid0;
    #pragma unroll 4
    for (; i < pin_start; i += stride) {              // streaming region
        float4 v = __ldcs(&x4[i]);
        vmin = fminf(vmin, fminf(fminf(v.x, v.y), fminf(v.z, v.w)));
        vmax = fmaxf(vmax, fmaxf(fmaxf(v.x, v.y), fmaxf(v.z, v.w)));
    }
    #pragma unroll 4
    for (; i < nv4; i += stride) {                    // pinned tail region
        float4 v = ld_pin(&x4[i], pol);
        vmin = fminf(vmin, fminf(fminf(v.x, v.y), fminf(v.z, v.w)));
        vmax = fmaxf(vmax, fmaxf(fmaxf(v.x, v.y), fmaxf(v.z, v.w)));
    }
    if (blockIdx.x == 0 && threadIdx.x < (n & 3)) {   // scalar tail (defensive)
        float v = xs[(nv4 << 2) + threadIdx.x];
        vmin = fminf(vmin, v);
        vmax = fmaxf(vmax, v);
    }

    #pragma unroll
    for (int o = 16; o; o >>= 1) {
        vmin = fminf(vmin, __shfl_xor_sync(0xFFFFFFFFu, vmin, o));
        vmax = fmaxf(vmax, __shfl_xor_sync(0xFFFFFFFFu, vmax, o));
    }
    const int wid = threadIdx.x >> 5;
    if ((threadIdx.x & 31) == 0) { smin[wid] = vmin; smax[wid] = vmax; }
    __syncthreads();

    // ------------------- barrier with folded reduction -------------------
    if (threadIdx.x == 0) {
        float bmin = smin[0], bmax = smax[0];
        #pragma unroll
        for (int w = 1; w < 8; w++) {
            bmin = fminf(bmin, smin[w]);
            bmax = fmaxf(bmax, smax[w]);
        }
        const int s = (int)(epoch0 & 1u);
        atomicMin(&g_mm[s][0], flipf(bmin));
        atomicMax(&g_mm[s][1], flipf(bmax));
        __threadfence();
        unsigned int old = atomicAdd(&g_count, 1u);
        if (old == NPART - 1) {
            // last arrival: finalize, publish, reset other slot, release
            float fmin = unflipf(ld_acq(&g_mm[s][0]));
            float fmax = unflipf(ld_acq(&g_mm[s][1]));
            float S = 31.0f / (fmax - fmin + 1e-6f);
            g_sb[s] = make_float2(S, -fmin * S);
            g_mm[s ^ 1][0] = 0xFFFFFFFFu;            // next replay's slot
            g_mm[s ^ 1][1] = 0u;
            atomicExch(&g_count, 0u);
            __threadfence();
            atomicAdd(&g_release, 1u);
            s_SB[0] = S;
            s_SB[1] = -fmin * S;
        } else {
            while (ld_acq(&g_release) == epoch0) __nanosleep(32);
            float2 sb = g_sb[s];                     // ordered after acquire
            s_SB[0] = sb.x;
            s_SB[1] = sb.y;
        }
    }
    __syncthreads();
    const float S = s_SB[0];
    const float B = s_SB[1];

    // ------------------- phase 2: transform (own indices, reversed) -------
    float4* __restrict__ o4 = (float4*)outs;
    if (tid0 < nv4) {
        const int last = tid0 + ((nv4 - 1 - tid0) / stride) * stride;
        #pragma unroll 2
        for (int j = last; j >= 0; j -= stride) {
            float4 v = __ldcs(&x4[j]);
            float4 r;
            r.x = auf_eval(v.x, S, B, tab);
            r.y = auf_eval(v.y, S, B, tab);
            r.z = auf_eval(v.z, S, B, tab);
            r.w = auf_eval(v.w, S, B, tab);
            __stcs(&o4[j], r);
        }
    }
    if (blockIdx.x == 0 && threadIdx.x < (n & 3)) {   // scalar tail
        const int e = (nv4 << 2) + threadIdx.x;
        outs[e] = auf_eval(xs[e], S, B, tab);
    }
}

// ---------------------------------------------------------------------------
// Launch: ONE kernel. No sync, no allocation -> graph-capturable.
// ---------------------------------------------------------------------------
extern "C" void kernel_launch(void* const* d_in, const int* in_sizes, int n_in,
                              void* d_out, int out_size) {
    const float* x  = (const float*)d_in[0];   // (64, 1048576) fp32
    const float* cp = (const float*)d_in[1];   // (32,) control points
    // d_in[2] = knots: uniform linspace(0,1,32) -> analytic, unused
    const int n = in_sizes[0];

    auf_fused_kernel<<<NPART, NTHREADS>>>(x, cp, (float*)d_out, n);
}